// round 11
// baseline (speedup 1.0000x reference)
#include <cuda_runtime.h>
#include <cuda_fp16.h>
#include <math.h>
#include <stdint.h>

// ---- model constants ----
#define TOK   32768
#define SEQL  8192
#define NBAT  4
#define HD    256
#define DI    512
#define DS    16
#define DCV   4
#define DR    16
#define IND   128
#define OUTD  10
#define NBLK  4
#define CL    128
#define NCH   (SEQL/CL)

// ---- scratch ----
__device__ __align__(256) float g_h [TOK*HD];
__device__ __align__(256) float g_xz[(size_t)TOK*2*DI];
__device__ __align__(256) float g_xc[(size_t)TOK*DI];
__device__ __align__(256) float g_dbc[(size_t)TOK*48];
__device__ __align__(256) float g_u [(size_t)TOK*DI];      // u = dt * xc
__device__ __align__(256) float g_p [(size_t)TOK*DI];      // p = exp(-dt)
__device__ __align__(256) float g_g [(size_t)TOK*2*HD];
__device__ __align__(256) float g_cs[NBAT*DI*NCH*DS];
__device__ __align__(256) float g_cp[NBAT*DI*NCH];
__device__ __align__(256) float g_hi2[NBAT*DI*NCH*DS];
__device__ __align__(256) float g_pp[NBAT*64*HD];
__device__ __align__(256) float g_pool[NBAT*HD];
__device__ __align__(256) __half g_ah[(size_t)TOK*DI];     // activation operand (fp16)
__device__ __align__(256) __half g_bh[(size_t)TOK*HD];     // gelu output operand
__device__ __align__(256) __half g_wh[262144];             // weight operand

// ================= helpers =================
__device__ __forceinline__ uint32_t smem_u32(const void* p) {
    uint32_t a;
    asm("{ .reg .u64 t; cvta.to.shared.u64 t, %1; cvt.u32.u64 %0, t; }" : "=r"(a) : "l"(p));
    return a;
}
__device__ __forceinline__ void cp16(uint32_t s, const void* g) {
    asm volatile("cp.async.cg.shared.global [%0], [%1], 16;" :: "r"(s), "l"(g));
}
__device__ __forceinline__ void ldm4(uint32_t* r, uint32_t a) {
    asm volatile("ldmatrix.sync.aligned.m8n8.x4.shared.b16 {%0,%1,%2,%3}, [%4];"
                 : "=r"(r[0]), "=r"(r[1]), "=r"(r[2]), "=r"(r[3]) : "r"(a));
}
__device__ __forceinline__ void mma16816(float* c, const uint32_t* a, const uint32_t* b) {
    asm volatile("mma.sync.aligned.m16n8k16.row.col.f32.f16.f16.f32 "
                 "{%0,%1,%2,%3}, {%4,%5,%6,%7}, {%8,%9}, {%0,%1,%2,%3};"
                 : "+f"(c[0]), "+f"(c[1]), "+f"(c[2]), "+f"(c[3])
                 : "r"(a[0]), "r"(a[1]), "r"(a[2]), "r"(a[3]), "r"(b[0]), "r"(b[1]));
}
// 64B rows, 4x16B segs, XOR swizzle: conflict-free ldmatrix
__device__ __forceinline__ uint32_t swz(int r, int s) {
    return (uint32_t)(r * 64 + (((s ^ (r >> 1)) & 3) << 4));
}
__device__ __forceinline__ float powi16(float p, int es) {
    float p2 = p*p, p4 = p2*p2, p8 = p4*p4, p16 = p8*p8;
    float r = 1.f;
    if (es & 1)  r *= p;
    if (es & 2)  r *= p2;
    if (es & 4)  r *= p4;
    if (es & 8)  r *= p8;
    if (es & 16) r *= p16;
    return r;
}

// ============ fp16 single-product GEMM: C[M,N] = A[M,K] * B[N,K]^T ===========
// CTA 128xBN, 8 warps (4m x 2n), K-chunk 32, 4-stage cp.async, 2 CTAs/SM.
// EPI: 0 plain fp32, 1 +bias, 2 GELU -> fp16, 3 first-48-col fp32 (ld 48)
template<int BN, int EPI>
__global__ void __launch_bounds__(256, 2)
gemm_mma(const __half* __restrict__ A, const __half* __restrict__ B,
         const float* __restrict__ bias,
         float* __restrict__ Cf, __half* __restrict__ Ch,
         int Ntot, int K)
{
    constexpr int WN  = BN / 2;
    constexpr int TNn = WN / 8;
    constexpr int ASZ = 128 * 64;           // 8KB A per stage
    constexpr int BSZ = BN * 64;
    constexpr int STG = ASZ + BSZ;          // 16KB (BN=128) / 12KB (BN=64)

    extern __shared__ char smem[];
    const int tid = threadIdx.x, wid = tid >> 5, lane = tid & 31;
    const int wm = wid & 3, wn = wid >> 2;
    const int mb = blockIdx.y * 128, nb = blockIdx.x * BN;
    const uint32_t sb = smem_u32(smem);

    float acc[2][TNn][4];
    #pragma unroll
    for (int i = 0; i < 2; i++)
        #pragma unroll
        for (int j = 0; j < TNn; j++)
            #pragma unroll
            for (int r = 0; r < 4; r++) acc[i][j][r] = 0.f;

    const int NC = K >> 5;

    auto issue = [&](int c) {
        const uint32_t st = sb + (c & 3) * STG;
        const int k0 = c << 5;
        #pragma unroll
        for (int i = 0; i < 2; i++) {              // A: 128 rows x 4 segs
            int idx = tid + i * 256;
            int r = idx >> 2, s = idx & 3;
            cp16(st + swz(r, s), A + (size_t)(mb + r) * K + k0 + s * 8);
        }
        #pragma unroll
        for (int i = 0; i < BN / 64; i++) {        // B: BN rows x 4 segs
            int idx = tid + i * 256;
            int r = (idx >> 2) % BN, s = idx & 3;
            cp16(st + ASZ + swz(r, s), B + (size_t)(nb + r) * K + k0 + s * 8);
        }
        asm volatile("cp.async.commit_group;");
    };

    issue(0);
    if (NC > 1) issue(1);
    if (NC > 2) issue(2);
    for (int c = 0; c < NC; c++) {
        if (c + 3 < NC)      { issue(c + 3); asm volatile("cp.async.wait_group 3;"); }
        else if (c + 2 < NC) { asm volatile("cp.async.wait_group 2;"); }
        else if (c + 1 < NC) { asm volatile("cp.async.wait_group 1;"); }
        else                 { asm volatile("cp.async.wait_group 0;"); }
        __syncthreads();
        const uint32_t st  = sb + (c & 3) * STG;
        const uint32_t stB = st + ASZ;
        #pragma unroll
        for (int kk = 0; kk < 2; kk++) {
            uint32_t a[2][4];
            #pragma unroll
            for (int i = 0; i < 2; i++) {
                int row = wm * 32 + i * 16 + (lane & 15);
                int seg = kk * 2 + (lane >> 4);
                ldm4(a[i], st + swz(row, seg));
            }
            #pragma unroll
            for (int jp = 0; jp < TNn / 2; jp++) {
                int rn = wn * WN + (jp * 2 + ((lane >> 4) & 1)) * 8 + (lane & 7);
                int seg = kk * 2 + ((lane >> 3) & 1);
                uint32_t b[4];
                ldm4(b, stB + swz(rn, seg));
                #pragma unroll
                for (int i = 0; i < 2; i++)
                    #pragma unroll
                    for (int jj = 0; jj < 2; jj++)
                        mma16816(acc[i][jp * 2 + jj], a[i], &b[jj * 2]);
            }
        }
        __syncthreads();
    }

    // epilogue
    #pragma unroll
    for (int i = 0; i < 2; i++)
        #pragma unroll
        for (int j = 0; j < TNn; j++)
            #pragma unroll
            for (int r = 0; r < 4; r++) {
                int m = mb + wm * 32 + i * 16 + (lane >> 2) + (r >> 1) * 8;
                int n = nb + wn * WN + j * 8 + (lane & 3) * 2 + (r & 1);
                float v = acc[i][j][r];
                if (EPI == 0) {
                    Cf[(size_t)m * Ntot + n] = v;
                } else if (EPI == 1) {
                    Cf[(size_t)m * Ntot + n] = v + bias[n];
                } else if (EPI == 2) {
                    v = 0.5f * v * (1.f + erff(v * 0.70710678118654752f));
                    Ch[(size_t)m * Ntot + n] = __float2half(v);
                } else {
                    if (n < 48) Cf[(size_t)m * 48 + n] = v;
                }
            }
}

// ======================= conversion kernels =======================
__global__ __launch_bounds__(256)
void convert_h(const float* __restrict__ src, __half* __restrict__ dst, int n)
{
    int i = blockIdx.x * 256 + threadIdx.x;
    if (i >= n) return;
    dst[i] = __float2half(src[i]);
}

__global__ __launch_bounds__(256)
void convert_hpad(const float* __restrict__ src, __half* __restrict__ dst,
                  int Nreal, int K, int total)
{
    int i = blockIdx.x * 256 + threadIdx.x;
    if (i >= total) return;
    int n = i / K, k = i % K;
    dst[i] = __float2half((n < Nreal) ? src[n * K + k] : 0.f);
}

// ======================= LayerNorm -> fp16 ==============
__global__ __launch_bounds__(256)
void layernorm_kernel(const float* __restrict__ in, const float* __restrict__ w,
                      const float* __restrict__ b)
{
    __shared__ float red[8], red2[8];
    const int t = blockIdx.x, tid = threadIdx.x;
    float v = in[(size_t)t * HD + tid];
    float s = v, s2 = v * v;
    #pragma unroll
    for (int o = 16; o; o >>= 1) {
        s  += __shfl_xor_sync(0xffffffffu, s,  o);
        s2 += __shfl_xor_sync(0xffffffffu, s2, o);
    }
    if ((tid & 31) == 0) { red[tid >> 5] = s; red2[tid >> 5] = s2; }
    __syncthreads();
    float ts = 0.f, ts2 = 0.f;
    #pragma unroll
    for (int i = 0; i < 8; i++) { ts += red[i]; ts2 += red2[i]; }
    float mu = ts * (1.f / HD);
    float var = ts2 * (1.f / HD) - mu * mu;
    float rstd = rsqrtf(var + 1e-5f);
    float ov = (v - mu) * rstd * w[tid] + b[tid];
    g_ah[(size_t)t * HD + tid] = __float2half(ov);
}

// ======================= causal depthwise conv + SiLU ======
__global__ __launch_bounds__(256)
void conv_silu_kernel(const float* __restrict__ cw, const float* __restrict__ cb)
{
    int idx = blockIdx.x * blockDim.x + threadIdx.x;
    if (idx >= TOK * DI) return;
    int t = idx / DI, d = idx % DI;
    int l = t & (SEQL - 1);
    float s = cb[d];
    #pragma unroll
    for (int k = 0; k < DCV; k++) {
        int lk = l - (DCV - 1) + k;
        if (lk >= 0)
            s = fmaf(g_xz[(size_t)(t - (DCV - 1) + k) * (2 * DI) + d], cw[d * DCV + k], s);
    }
    float o = s / (1.f + __expf(-s));
    g_xc[idx] = o;
    g_ah[idx] = __float2half(o);
}

// ============== u = softplus(...) * xc; p = exp(-dt) =====
__global__ __launch_bounds__(256)
void dtproj_kernel(const float* __restrict__ dtw, const float* __restrict__ dtb)
{
    int idx = blockIdx.x * blockDim.x + threadIdx.x;
    if (idx >= TOK * DI) return;
    int t = idx / DI, d = idx % DI;
    const float* r = g_dbc + (size_t)t * 48;
    const float* w = dtw + d * DR;
    float s = dtb[d];
    #pragma unroll
    for (int k = 0; k < DR; k++) s = fmaf(r[k], w[k], s);
    float dtv = (s > 20.f) ? s : log1pf(__expf(s));
    g_u[idx] = dtv * g_xc[idx];
    g_p[idx] = __expf(-dtv);
}

// ======================= scan pass A ======================
__global__ __launch_bounds__(256)
void scan_passA(const float* __restrict__ a_log)
{
    int gt = blockIdx.x * blockDim.x + threadIdx.x;
    int gid = gt >> 4, lane = gt & 15;
    if (gid >= NBAT * NCH * DI) return;
    int d = gid % DI;
    int chunk = (gid / DI) % NCH;
    int b = gid / (DI * NCH);
    int es = (int)lrintf(__expf(a_log[d * DS + lane]));
    float h = 0.f, cp = 1.f;
    size_t tok0 = (size_t)b * SEQL + (size_t)chunk * CL;
    for (int t = 0; t < CL; t++) {
        size_t tok = tok0 + t;
        float uv = g_u[tok * DI + d];
        float pv = g_p[tok * DI + d];
        float Bv = g_dbc[tok * 48 + DR + lane];
        h = fmaf(h, powi16(pv, es), uv * Bv);
        cp *= pv;
    }
    int bd = b * DI + d;
    g_cs[(size_t)(bd * NCH + chunk) * DS + lane] = h;
    if (lane == 0) g_cp[bd * NCH + chunk] = cp;
}

// =================== chunk-level recurrence ==================
__global__ __launch_bounds__(256)
void scan_combine(const float* __restrict__ a_log)
{
    int idx = blockIdx.x * blockDim.x + threadIdx.x;
    if (idx >= NBAT * DI * DS) return;
    int s = idx & 15, bd = idx >> 4;
    int d = bd % DI;
    int es = (int)lrintf(__expf(a_log[d * DS + s]));
    float hsum = 0.f;
    for (int c = 0; c < NCH; c++) {
        g_hi2[(size_t)(bd * NCH + c) * DS + s] = hsum;
        float P = powi16(g_cp[bd * NCH + c], es);
        hsum = fmaf(hsum, P, g_cs[(size_t)(bd * NCH + c) * DS + s]);
    }
}

// == scan pass B: y -> fp16 ======
__global__ __launch_bounds__(256)
void scan_passB(const float* __restrict__ a_log, const float* __restrict__ dskip)
{
    int gt = blockIdx.x * blockDim.x + threadIdx.x;
    int gid = gt >> 4, lane = gt & 15;
    if (gid >= NBAT * NCH * DI) return;
    int d = gid % DI;
    int chunk = (gid / DI) % NCH;
    int b = gid / (DI * NCH);
    int bd = b * DI + d;
    int es = (int)lrintf(__expf(a_log[d * DS + lane]));
    float h = g_hi2[(size_t)(bd * NCH + chunk) * DS + lane];
    float dsk = dskip[d];
    size_t tok0 = (size_t)b * SEQL + (size_t)chunk * CL;
    for (int t = 0; t < CL; t++) {
        size_t tok = tok0 + t;
        float uv = g_u[tok * DI + d];
        float pv = g_p[tok * DI + d];
        float Bv = g_dbc[tok * 48 + DR + lane];
        float Cv = g_dbc[tok * 48 + 2 * DR + lane];
        h = fmaf(h, powi16(pv, es), uv * Bv);
        float yv = h * Cv;
        #pragma unroll
        for (int o = 8; o; o >>= 1) yv += __shfl_xor_sync(0xffffffffu, yv, o);
        if (lane == 0) {
            float xv = g_xc[tok * DI + d];
            float z = g_xz[tok * (2 * DI) + DI + d];
            float sz = z / (1.f + __expf(-z));
            float out = (yv + xv * dsk) * sz;
            g_ah[tok * DI + d] = __float2half(out);
        }
    }
}

// ======================= GLU + residual =======================
__global__ __launch_bounds__(256)
void glu_res_kernel()
{
    int idx = blockIdx.x * blockDim.x + threadIdx.x;
    if (idx >= TOK * HD) return;
    int t = idx / HD, hh = idx % HD;
    float a  = g_g[(size_t)t * 2 * HD + hh];
    float zq = g_g[(size_t)t * 2 * HD + HD + hh];
    g_h[idx] += a / (1.f + __expf(-zq));
}

// ======================= mean pool + decoder ====================
__global__ __launch_bounds__(256)
void pool1_kernel()
{
    int b = blockIdx.x >> 6;
    int part = blockIdx.x & 63;
    int hh = threadIdx.x;
    float s = 0.f;
    size_t base = (size_t)b * SEQL + (size_t)part * 128;
    for (int l = 0; l < 128; l++) s += g_h[(base + l) * HD + hh];
    g_pp[(size_t)blockIdx.x * HD + hh] = s;
}

__global__ __launch_bounds__(256)
void pool2_kernel()
{
    int b = blockIdx.x, hh = threadIdx.x;
    float s = 0.f;
    for (int c = 0; c < 64; c++) s += g_pp[(size_t)(b * 64 + c) * HD + hh];
    g_pool[b * HD + hh] = s * (1.f / SEQL);
}

__global__ void dec_kernel(const float* __restrict__ dw, const float* __restrict__ db,
                           float* __restrict__ out)
{
    int b = blockIdx.x, lane = threadIdx.x;
    float v = -1e30f;
    if (lane < OUTD) {
        float s = db[lane];
        for (int k = 0; k < HD; k++) s = fmaf(g_pool[b * HD + k], dw[lane * HD + k], s);
        v = s;
    }
    float m = v;
    #pragma unroll
    for (int o = 16; o; o >>= 1) m = fmaxf(m, __shfl_xor_sync(0xffffffffu, m, o));
    float e = (lane < OUTD) ? __expf(v - m) : 0.f;
    float se = e;
    #pragma unroll
    for (int o = 16; o; o >>= 1) se += __shfl_xor_sync(0xffffffffu, se, o);
    if (lane < OUTD) out[b * OUTD + lane] = e / se;
}

// ======================= host launcher ==========================================
extern "C" void kernel_launch(void* const* d_in, const int* in_sizes, int n_in,
                              void* d_out, int out_size)
{
    const float* x         = (const float*)d_in[0];
    const float* enc_w     = (const float*)d_in[1];
    const float* enc_b     = (const float*)d_in[2];
    const float* norm_w    = (const float*)d_in[3];
    const float* norm_b    = (const float*)d_in[4];
    const float* in_proj_w = (const float*)d_in[5];
    const float* conv_w    = (const float*)d_in[6];
    const float* conv_b    = (const float*)d_in[7];
    const float* xproj_w   = (const float*)d_in[8];
    const float* dtproj_w  = (const float*)d_in[9];
    const float* dtproj_b  = (const float*)d_in[10];
    const float* A_log     = (const float*)d_in[11];
    const float* D_skip    = (const float*)d_in[12];
    const float* outproj_w = (const float*)d_in[13];
    const float* glu_w     = (const float*)d_in[14];
    const float* glu_b     = (const float*)d_in[15];
    const float* dec_w     = (const float*)d_in[16];
    const float* dec_b     = (const float*)d_in[17];
    float* out = (float*)d_out;

    float *p_h, *p_xz, *p_dbc, *p_g;
    __half *p_ah, *p_bh, *p_wh;
    cudaGetSymbolAddress((void**)&p_h,   g_h);
    cudaGetSymbolAddress((void**)&p_xz,  g_xz);
    cudaGetSymbolAddress((void**)&p_dbc, g_dbc);
    cudaGetSymbolAddress((void**)&p_g,   g_g);
    cudaGetSymbolAddress((void**)&p_ah,  g_ah);
    cudaGetSymbolAddress((void**)&p_bh,  g_bh);
    cudaGetSymbolAddress((void**)&p_wh,  g_wh);

    const int SM128 = 4 * (128 * 64 + 128 * 64);  // 65536
    const int SM64  = 4 * (128 * 64 + 64 * 64);   // 49152
    cudaFuncSetAttribute(gemm_mma<128,0>, cudaFuncAttributeMaxDynamicSharedMemorySize, SM128);
    cudaFuncSetAttribute(gemm_mma<128,1>, cudaFuncAttributeMaxDynamicSharedMemorySize, SM128);
    cudaFuncSetAttribute(gemm_mma<128,2>, cudaFuncAttributeMaxDynamicSharedMemorySize, SM128);
    cudaFuncSetAttribute(gemm_mma<64,3>,  cudaFuncAttributeMaxDynamicSharedMemorySize, SM64);

    // encoder: h = x @ enc_w^T + enc_b
    convert_h<<<(TOK*IND + 255)/256, 256>>>(x, p_ah, TOK*IND);
    convert_h<<<(HD*IND + 255)/256, 256>>>(enc_w, p_wh, HD*IND);
    gemm_mma<128,1><<<dim3(2, 256), 256, SM128>>>(p_ah, p_wh, enc_b, p_h, nullptr, HD, IND);

    for (int i = 0; i < NBLK; i++) {
        const float* alog_i = A_log + (size_t)i * DI * DS;
        layernorm_kernel<<<TOK, 256>>>(p_h, norm_w + i * HD, norm_b + i * HD);
        convert_h<<<(2*DI*HD + 255)/256, 256>>>(in_proj_w + (size_t)i * 2*DI*HD, p_wh, 2*DI*HD);
        gemm_mma<128,0><<<dim3(8, 256), 256, SM128>>>(p_ah, p_wh, nullptr, p_xz, nullptr, 2*DI, HD);
        conv_silu_kernel<<<TOK * DI / 256, 256>>>(conv_w + i * DI * DCV, conv_b + i * DI);
        convert_hpad<<<(64*DI + 255)/256, 256>>>(xproj_w + (size_t)i * 48 * DI, p_wh, 48, DI, 64*DI);
        gemm_mma<64,3><<<dim3(1, 256), 256, SM64>>>(p_ah, p_wh, nullptr, p_dbc, nullptr, 64, DI);
        dtproj_kernel<<<TOK * DI / 256, 256>>>(dtproj_w + i * DI * DR, dtproj_b + i * DI);
        scan_passA<<<NBAT * NCH * DI * 16 / 256, 256>>>(alog_i);
        scan_combine<<<NBAT * DI * DS / 256, 256>>>(alog_i);
        scan_passB<<<NBAT * NCH * DI * 16 / 256, 256>>>(alog_i, D_skip + i * DI);
        convert_h<<<(HD*DI + 255)/256, 256>>>(outproj_w + (size_t)i * HD * DI, p_wh, HD*DI);
        gemm_mma<128,2><<<dim3(2, 256), 256, SM128>>>(p_ah, p_wh, nullptr, nullptr, p_bh, HD, DI);
        convert_h<<<(2*HD*HD + 255)/256, 256>>>(glu_w + (size_t)i * 2*HD*HD, p_wh, 2*HD*HD);
        gemm_mma<128,1><<<dim3(4, 256), 256, SM128>>>(p_bh, p_wh, glu_b + i * 2 * HD, p_g, nullptr, 2*HD, HD);
        glu_res_kernel<<<TOK * HD / 256, 256>>>();
    }

    pool1_kernel<<<NBAT * 64, 256>>>();
    pool2_kernel<<<NBAT, 256>>>();
    dec_kernel<<<NBAT, 32>>>(dec_w, dec_b, out);
}

// round 13
// speedup vs baseline: 1.0233x; 1.0233x over previous
#include <cuda_runtime.h>
#include <cuda_fp16.h>
#include <math.h>
#include <stdint.h>

// ---- model constants ----
#define TOK   32768
#define SEQL  8192
#define NBAT  4
#define HD    256
#define DI    512
#define DS    16
#define DCV   4
#define DR    16
#define IND   128
#define OUTD  10
#define NBLK  4
#define CL    128
#define NCH   (SEQL/CL)
#define KC    64          // K-chunk (64 fp16 = 128B row)

// ---- scratch ----
__device__ __align__(256) float g_h [TOK*HD];
__device__ __align__(256) float g_xz[(size_t)TOK*2*DI];
__device__ __align__(256) float g_xc[(size_t)TOK*DI];
__device__ __align__(256) float g_dbc[(size_t)TOK*48];
__device__ __align__(256) float g_u [(size_t)TOK*DI];      // u = dt * xc
__device__ __align__(256) float g_p [(size_t)TOK*DI];      // p = exp(-dt)
__device__ __align__(256) float g_g [(size_t)TOK*2*HD];
__device__ __align__(256) float g_cs[NBAT*DI*NCH*DS];
__device__ __align__(256) float g_cp[NBAT*DI*NCH];
__device__ __align__(256) float g_hi2[NBAT*DI*NCH*DS];
__device__ __align__(256) float g_pp[NBAT*64*HD];
__device__ __align__(256) float g_pool[NBAT*HD];
__device__ __align__(256) __half g_ah[(size_t)TOK*DI];     // activation operand
__device__ __align__(256) __half g_bh[(size_t)TOK*HD];     // gelu output operand
__device__ __align__(256) __half g_wh[262144];             // weight operand (main)
__device__ __align__(256) __half g_wh2[32768];             // enc_w (profiling order)

// ================= helpers =================
__device__ __forceinline__ uint32_t smem_u32(const void* p) {
    uint32_t a;
    asm("{ .reg .u64 t; cvta.to.shared.u64 t, %1; cvt.u32.u64 %0, t; }" : "=r"(a) : "l"(p));
    return a;
}
__device__ __forceinline__ void cp16(uint32_t s, const void* g) {
    asm volatile("cp.async.cg.shared.global [%0], [%1], 16;" :: "r"(s), "l"(g));
}
__device__ __forceinline__ void ldm4(uint32_t* r, uint32_t a) {
    asm volatile("ldmatrix.sync.aligned.m8n8.x4.shared.b16 {%0,%1,%2,%3}, [%4];"
                 : "=r"(r[0]), "=r"(r[1]), "=r"(r[2]), "=r"(r[3]) : "r"(a));
}
__device__ __forceinline__ void mma16816(float* c, const uint32_t* a, const uint32_t* b) {
    asm volatile("mma.sync.aligned.m16n8k16.row.col.f32.f16.f16.f32 "
                 "{%0,%1,%2,%3}, {%4,%5,%6,%7}, {%8,%9}, {%0,%1,%2,%3};"
                 : "+f"(c[0]), "+f"(c[1]), "+f"(c[2]), "+f"(c[3])
                 : "r"(a[0]), "r"(a[1]), "r"(a[2]), "r"(a[3]), "r"(b[0]), "r"(b[1]));
}
// 128B rows, 8x16B segs, XOR swizzle over full 8-row period: conflict-free
__device__ __forceinline__ uint32_t swz(int r, int s) {
    return (uint32_t)(r * 128 + ((s ^ (r & 7)) << 4));
}
__device__ __forceinline__ float powi16(float p, int es) {
    float p2 = p*p, p4 = p2*p2, p8 = p4*p4, p16 = p8*p8;
    float r = 1.f;
    if (es & 1)  r *= p;
    if (es & 2)  r *= p2;
    if (es & 4)  r *= p4;
    if (es & 8)  r *= p8;
    if (es & 16) r *= p16;
    return r;
}

// ============ fp16 GEMM: C[M,N] = A[M,K] * B[N,K]^T, K-chunk 64 ===========
// CTA 128xBN, 8 warps (4m x 2n, warp 32x64 for BN=128), 3-stage cp.async, 2 CTAs/SM.
// EPI: 0 plain fp32, 1 +bias, 2 GELU -> fp16, 3 first-48-col fp32 (ld 48)
template<int BN, int EPI>
__global__ void __launch_bounds__(256, 2)
gemm_mma(const __half* __restrict__ A, const __half* __restrict__ B,
         const float* __restrict__ bias,
         float* __restrict__ Cf, __half* __restrict__ Ch,
         int Ntot, int K)
{
    constexpr int WN  = BN / 2;
    constexpr int TNn = WN / 8;
    constexpr int ASZ = 128 * 128;          // 16KB A per stage
    constexpr int BSZ = BN * 128;
    constexpr int STG = ASZ + BSZ;          // 32KB (BN=128) / 24KB (BN=64)

    extern __shared__ char smem[];
    const int tid = threadIdx.x, wid = tid >> 5, lane = tid & 31;
    const int wm = wid & 3, wn = wid >> 2;
    const int mb = blockIdx.y * 128, nb = blockIdx.x * BN;
    const uint32_t sb = smem_u32(smem);

    float acc[2][TNn][4];
    #pragma unroll
    for (int i = 0; i < 2; i++)
        #pragma unroll
        for (int j = 0; j < TNn; j++)
            #pragma unroll
            for (int r = 0; r < 4; r++) acc[i][j][r] = 0.f;

    const int NC = K / KC;

    auto issue = [&](int c) {
        const uint32_t st = sb + (c % 3) * STG;
        const int k0 = c * KC;
        #pragma unroll
        for (int i = 0; i < 4; i++) {              // A: 128 rows x 8 segs
            int idx = tid + i * 256;
            int r = idx >> 3, s = idx & 7;
            cp16(st + swz(r, s), A + (size_t)(mb + r) * K + k0 + s * 8);
        }
        #pragma unroll
        for (int i = 0; i < BN / 32; i++) {        // B: BN rows x 8 segs
            int idx = tid + i * 256;
            int r = (idx >> 3) % BN, s = idx & 7;
            cp16(st + ASZ + swz(r, s), B + (size_t)(nb + r) * K + k0 + s * 8);
        }
        asm volatile("cp.async.commit_group;");
    };

    issue(0);
    if (NC > 1) issue(1);
    if (NC > 2) issue(2);
    for (int c = 0; c < NC; c++) {
        if (c + 2 < NC)      { asm volatile("cp.async.wait_group 2;"); }
        else if (c + 1 < NC) { asm volatile("cp.async.wait_group 1;"); }
        else                 { asm volatile("cp.async.wait_group 0;"); }
        __syncthreads();
        const uint32_t st  = sb + (c % 3) * STG;
        const uint32_t stB = st + ASZ;
        #pragma unroll
        for (int kk = 0; kk < 4; kk++) {           // 4 x k16 slices
            uint32_t a[2][4];
            #pragma unroll
            for (int i = 0; i < 2; i++) {
                int row = wm * 32 + i * 16 + (lane & 15);
                int seg = kk * 2 + (lane >> 4);
                ldm4(a[i], st + swz(row, seg));
            }
            #pragma unroll
            for (int jp = 0; jp < TNn / 2; jp++) {
                int rn = wn * WN + (jp * 2 + ((lane >> 4) & 1)) * 8 + (lane & 7);
                int seg = kk * 2 + ((lane >> 3) & 1);
                uint32_t b[4];
                ldm4(b, stB + swz(rn, seg));
                #pragma unroll
                for (int i = 0; i < 2; i++)
                    #pragma unroll
                    for (int jj = 0; jj < 2; jj++)
                        mma16816(acc[i][jp * 2 + jj], a[i], &b[jj * 2]);
            }
        }
        __syncthreads();
        if (c + 3 < NC) issue(c + 3);
    }

    // epilogue
    #pragma unroll
    for (int i = 0; i < 2; i++)
        #pragma unroll
        for (int j = 0; j < TNn; j++)
            #pragma unroll
            for (int r = 0; r < 4; r++) {
                int m = mb + wm * 32 + i * 16 + (lane >> 2) + (r >> 1) * 8;
                int n = nb + wn * WN + j * 8 + (lane & 3) * 2 + (r & 1);
                float v = acc[i][j][r];
                if (EPI == 0) {
                    Cf[(size_t)m * Ntot + n] = v;
                } else if (EPI == 1) {
                    Cf[(size_t)m * Ntot + n] = v + bias[n];
                } else if (EPI == 2) {
                    v = 0.5f * v * (1.f + erff(v * 0.70710678118654752f));
                    Ch[(size_t)m * Ntot + n] = __float2half(v);
                } else {
                    if (n < 48) Cf[(size_t)m * 48 + n] = v;
                }
            }
}

// ======================= conversion kernels =======================
__global__ __launch_bounds__(256)
void convert_h(const float* __restrict__ src, __half* __restrict__ dst, int n)
{
    int i = blockIdx.x * 256 + threadIdx.x;
    if (i >= n) return;
    dst[i] = __float2half(src[i]);
}

__global__ __launch_bounds__(256)
void convert_hpad(const float* __restrict__ src, __half* __restrict__ dst,
                  int Nreal, int K, int total)
{
    int i = blockIdx.x * 256 + threadIdx.x;
    if (i >= total) return;
    int n = i / K, k = i % K;
    dst[i] = __float2half((n < Nreal) ? src[n * K + k] : 0.f);
}

// ======================= LayerNorm -> fp16 ==============
__global__ __launch_bounds__(256)
void layernorm_kernel(const float* __restrict__ in, const float* __restrict__ w,
                      const float* __restrict__ b)
{
    __shared__ float red[8], red2[8];
    const int t = blockIdx.x, tid = threadIdx.x;
    float v = in[(size_t)t * HD + tid];
    float s = v, s2 = v * v;
    #pragma unroll
    for (int o = 16; o; o >>= 1) {
        s  += __shfl_xor_sync(0xffffffffu, s,  o);
        s2 += __shfl_xor_sync(0xffffffffu, s2, o);
    }
    if ((tid & 31) == 0) { red[tid >> 5] = s; red2[tid >> 5] = s2; }
    __syncthreads();
    float ts = 0.f, ts2 = 0.f;
    #pragma unroll
    for (int i = 0; i < 8; i++) { ts += red[i]; ts2 += red2[i]; }
    float mu = ts * (1.f / HD);
    float var = ts2 * (1.f / HD) - mu * mu;
    float rstd = rsqrtf(var + 1e-5f);
    float ov = (v - mu) * rstd * w[tid] + b[tid];
    g_ah[(size_t)t * HD + tid] = __float2half(ov);
}

// ======================= causal depthwise conv + SiLU ======
__global__ __launch_bounds__(256)
void conv_silu_kernel(const float* __restrict__ cw, const float* __restrict__ cb)
{
    int idx = blockIdx.x * blockDim.x + threadIdx.x;
    if (idx >= TOK * DI) return;
    int t = idx / DI, d = idx % DI;
    int l = t & (SEQL - 1);
    float s = cb[d];
    #pragma unroll
    for (int k = 0; k < DCV; k++) {
        int lk = l - (DCV - 1) + k;
        if (lk >= 0)
            s = fmaf(g_xz[(size_t)(t - (DCV - 1) + k) * (2 * DI) + d], cw[d * DCV + k], s);
    }
    float o = s / (1.f + __expf(-s));
    g_xc[idx] = o;
    g_ah[idx] = __float2half(o);
}

// ============== u = softplus(...) * xc; p = exp(-dt) =====
__global__ __launch_bounds__(256)
void dtproj_kernel(const float* __restrict__ dtw, const float* __restrict__ dtb)
{
    int idx = blockIdx.x * blockDim.x + threadIdx.x;
    if (idx >= TOK * DI) return;
    int t = idx / DI, d = idx % DI;
    const float* r = g_dbc + (size_t)t * 48;
    const float* w = dtw + d * DR;
    float s = dtb[d];
    #pragma unroll
    for (int k = 0; k < DR; k++) s = fmaf(r[k], w[k], s);
    float dtv = (s > 20.f) ? s : log1pf(__expf(s));
    g_u[idx] = dtv * g_xc[idx];
    g_p[idx] = __expf(-dtv);
}

// ======================= scan pass A ======================
__global__ __launch_bounds__(256)
void scan_passA(const float* __restrict__ a_log)
{
    int gt = blockIdx.x * blockDim.x + threadIdx.x;
    int gid = gt >> 4, lane = gt & 15;
    if (gid >= NBAT * NCH * DI) return;
    int d = gid % DI;
    int chunk = (gid / DI) % NCH;
    int b = gid / (DI * NCH);
    int es = (int)lrintf(__expf(a_log[d * DS + lane]));
    float h = 0.f, cp = 1.f;
    size_t tok0 = (size_t)b * SEQL + (size_t)chunk * CL;
    for (int t = 0; t < CL; t++) {
        size_t tok = tok0 + t;
        float uv = g_u[tok * DI + d];
        float pv = g_p[tok * DI + d];
        float Bv = g_dbc[tok * 48 + DR + lane];
        h = fmaf(h, powi16(pv, es), uv * Bv);
        cp *= pv;
    }
    int bd = b * DI + d;
    g_cs[(size_t)(bd * NCH + chunk) * DS + lane] = h;
    if (lane == 0) g_cp[bd * NCH + chunk] = cp;
}

// =================== chunk-level recurrence ==================
__global__ __launch_bounds__(256)
void scan_combine(const float* __restrict__ a_log)
{
    int idx = blockIdx.x * blockDim.x + threadIdx.x;
    if (idx >= NBAT * DI * DS) return;
    int s = idx & 15, bd = idx >> 4;
    int d = bd % DI;
    int es = (int)lrintf(__expf(a_log[d * DS + s]));
    float hsum = 0.f;
    for (int c = 0; c < NCH; c++) {
        g_hi2[(size_t)(bd * NCH + c) * DS + s] = hsum;
        float P = powi16(g_cp[bd * NCH + c], es);
        hsum = fmaf(hsum, P, g_cs[(size_t)(bd * NCH + c) * DS + s]);
    }
}

// == scan pass B: y -> fp16 ======
__global__ __launch_bounds__(256)
void scan_passB(const float* __restrict__ a_log, const float* __restrict__ dskip)
{
    int gt = blockIdx.x * blockDim.x + threadIdx.x;
    int gid = gt >> 4, lane = gt & 15;
    if (gid >= NBAT * NCH * DI) return;
    int d = gid % DI;
    int chunk = (gid / DI) % NCH;
    int b = gid / (DI * NCH);
    int bd = b * DI + d;
    int es = (int)lrintf(__expf(a_log[d * DS + lane]));
    float h = g_hi2[(size_t)(bd * NCH + chunk) * DS + lane];
    float dsk = dskip[d];
    size_t tok0 = (size_t)b * SEQL + (size_t)chunk * CL;
    for (int t = 0; t < CL; t++) {
        size_t tok = tok0 + t;
        float uv = g_u[tok * DI + d];
        float pv = g_p[tok * DI + d];
        float Bv = g_dbc[tok * 48 + DR + lane];
        float Cv = g_dbc[tok * 48 + 2 * DR + lane];
        h = fmaf(h, powi16(pv, es), uv * Bv);
        float yv = h * Cv;
        #pragma unroll
        for (int o = 8; o; o >>= 1) yv += __shfl_xor_sync(0xffffffffu, yv, o);
        if (lane == 0) {
            float xv = g_xc[tok * DI + d];
            float z = g_xz[tok * (2 * DI) + DI + d];
            float sz = z / (1.f + __expf(-z));
            float out = (yv + xv * dsk) * sz;
            g_ah[tok * DI + d] = __float2half(out);
        }
    }
}

// ======================= GLU + residual =======================
__global__ __launch_bounds__(256)
void glu_res_kernel()
{
    int idx = blockIdx.x * blockDim.x + threadIdx.x;
    if (idx >= TOK * HD) return;
    int t = idx / HD, hh = idx % HD;
    float a  = g_g[(size_t)t * 2 * HD + hh];
    float zq = g_g[(size_t)t * 2 * HD + HD + hh];
    g_h[idx] += a / (1.f + __expf(-zq));
}

// ======================= mean pool + decoder ====================
__global__ __launch_bounds__(256)
void pool1_kernel()
{
    int b = blockIdx.x >> 6;
    int part = blockIdx.x & 63;
    int hh = threadIdx.x;
    float s = 0.f;
    size_t base = (size_t)b * SEQL + (size_t)part * 128;
    for (int l = 0; l < 128; l++) s += g_h[(base + l) * HD + hh];
    g_pp[(size_t)blockIdx.x * HD + hh] = s;
}

__global__ __launch_bounds__(256)
void pool2_kernel()
{
    int b = blockIdx.x, hh = threadIdx.x;
    float s = 0.f;
    for (int c = 0; c < 64; c++) s += g_pp[(size_t)(b * 64 + c) * HD + hh];
    g_pool[b * HD + hh] = s * (1.f / SEQL);
}

__global__ void dec_kernel(const float* __restrict__ dw, const float* __restrict__ db,
                           float* __restrict__ out)
{
    int b = blockIdx.x, lane = threadIdx.x;
    float v = -1e30f;
    if (lane < OUTD) {
        float s = db[lane];
        for (int k = 0; k < HD; k++) s = fmaf(g_pool[b * HD + k], dw[lane * HD + k], s);
        v = s;
    }
    float m = v;
    #pragma unroll
    for (int o = 16; o; o >>= 1) m = fmaxf(m, __shfl_xor_sync(0xffffffffu, m, o));
    float e = (lane < OUTD) ? __expf(v - m) : 0.f;
    float se = e;
    #pragma unroll
    for (int o = 16; o; o >>= 1) se += __shfl_xor_sync(0xffffffffu, se, o);
    if (lane < OUTD) out[b * OUTD + lane] = e / se;
}

// ======================= host launcher ==========================================
extern "C" void kernel_launch(void* const* d_in, const int* in_sizes, int n_in,
                              void* d_out, int out_size)
{
    const float* x         = (const float*)d_in[0];
    const float* enc_w     = (const float*)d_in[1];
    const float* enc_b     = (const float*)d_in[2];
    const float* norm_w    = (const float*)d_in[3];
    const float* norm_b    = (const float*)d_in[4];
    const float* in_proj_w = (const float*)d_in[5];
    const float* conv_w    = (const float*)d_in[6];
    const float* conv_b    = (const float*)d_in[7];
    const float* xproj_w   = (const float*)d_in[8];
    const float* dtproj_w  = (const float*)d_in[9];
    const float* dtproj_b  = (const float*)d_in[10];
    const float* A_log     = (const float*)d_in[11];
    const float* D_skip    = (const float*)d_in[12];
    const float* outproj_w = (const float*)d_in[13];
    const float* glu_w     = (const float*)d_in[14];
    const float* glu_b     = (const float*)d_in[15];
    const float* dec_w     = (const float*)d_in[16];
    const float* dec_b     = (const float*)d_in[17];
    float* out = (float*)d_out;

    float *p_h, *p_xz, *p_dbc, *p_g;
    __half *p_ah, *p_bh, *p_wh, *p_wh2;
    cudaGetSymbolAddress((void**)&p_h,   g_h);
    cudaGetSymbolAddress((void**)&p_xz,  g_xz);
    cudaGetSymbolAddress((void**)&p_dbc, g_dbc);
    cudaGetSymbolAddress((void**)&p_g,   g_g);
    cudaGetSymbolAddress((void**)&p_ah,  g_ah);
    cudaGetSymbolAddress((void**)&p_bh,  g_bh);
    cudaGetSymbolAddress((void**)&p_wh,  g_wh);
    cudaGetSymbolAddress((void**)&p_wh2, g_wh2);

    const int SM128 = 3 * (128 * 128 + 128 * 128);  // 98304
    const int SM64  = 3 * (128 * 128 + 64 * 128);   // 73728
    cudaFuncSetAttribute(gemm_mma<128,0>, cudaFuncAttributeMaxDynamicSharedMemorySize, SM128);
    cudaFuncSetAttribute(gemm_mma<128,1>, cudaFuncAttributeMaxDynamicSharedMemorySize, SM128);
    cudaFuncSetAttribute(gemm_mma<128,2>, cudaFuncAttributeMaxDynamicSharedMemorySize, SM128);
    cudaFuncSetAttribute(gemm_mma<64,3>,  cudaFuncAttributeMaxDynamicSharedMemorySize, SM64);

    // launch order arranged so launch #4 (profiled by ncu) is gemm_mma (encoder)
    convert_h<<<(TOK*IND + 255)/256, 256>>>(x, p_ah, TOK*IND);                       // 1
    convert_h<<<(HD*IND + 255)/256, 256>>>(enc_w, p_wh2, HD*IND);                    // 2
    convert_h<<<(2*DI*HD + 255)/256, 256>>>(in_proj_w, p_wh, 2*DI*HD);               // 3 (block 0)
    gemm_mma<128,1><<<dim3(2, 256), 256, SM128>>>(p_ah, p_wh2, enc_b, p_h, nullptr,  // 4 <- PROFILED
                                                  HD, IND);

    for (int i = 0; i < NBLK; i++) {
        const float* alog_i = A_log + (size_t)i * DI * DS;
        layernorm_kernel<<<TOK, 256>>>(p_h, norm_w + i * HD, norm_b + i * HD);
        if (i > 0)
            convert_h<<<(2*DI*HD + 255)/256, 256>>>(in_proj_w + (size_t)i * 2*DI*HD, p_wh, 2*DI*HD);
        gemm_mma<128,0><<<dim3(8, 256), 256, SM128>>>(p_ah, p_wh, nullptr, p_xz, nullptr, 2*DI, HD);
        conv_silu_kernel<<<TOK * DI / 256, 256>>>(conv_w + i * DI * DCV, conv_b + i * DI);
        convert_hpad<<<(64*DI + 255)/256, 256>>>(xproj_w + (size_t)i * 48 * DI, p_wh, 48, DI, 64*DI);
        gemm_mma<64,3><<<dim3(1, 256), 256, SM64>>>(p_ah, p_wh, nullptr, p_dbc, nullptr, 64, DI);
        dtproj_kernel<<<TOK * DI / 256, 256>>>(dtproj_w + i * DI * DR, dtproj_b + i * DI);
        scan_passA<<<NBAT * NCH * DI * 16 / 256, 256>>>(alog_i);
        scan_combine<<<NBAT * DI * DS / 256, 256>>>(alog_i);
        scan_passB<<<NBAT * NCH * DI * 16 / 256, 256>>>(alog_i, D_skip + i * DI);
        convert_h<<<(HD*DI + 255)/256, 256>>>(outproj_w + (size_t)i * HD * DI, p_wh, HD*DI);
        gemm_mma<128,2><<<dim3(2, 256), 256, SM128>>>(p_ah, p_wh, nullptr, nullptr, p_bh, HD, DI);
        convert_h<<<(2*HD*HD + 255)/256, 256>>>(glu_w + (size_t)i * 2*HD*HD, p_wh, 2*HD*HD);
        gemm_mma<128,1><<<dim3(4, 256), 256, SM128>>>(p_bh, p_wh, glu_b + i * 2 * HD, p_g, nullptr, 2*HD, HD);
        glu_res_kernel<<<TOK * HD / 256, 256>>>();
    }

    pool1_kernel<<<NBAT * 64, 256>>>();
    pool2_kernel<<<NBAT, 256>>>();
    dec_kernel<<<NBAT, 32>>>(dec_w, dec_b, out);
}